// round 1
// baseline (speedup 1.0000x reference)
#include <cuda_runtime.h>

#define BATCH 2
#define SEQ   2048
#define NH    8
#define HD    64
#define EMB   512
#define EDIM  16
#define MROWS (BATCH*SEQ)   // 4096

// Scratch (no cudaMalloc allowed): 4 x 8MB
__device__ float g_q[BATCH*NH*SEQ*HD];
__device__ float g_k[BATCH*NH*SEQ*HD];
__device__ float g_v[BATCH*NH*SEQ*HD];
__device__ float g_ao[MROWS*EMB];

// ---------------------------------------------------------------------------
// SGEMM core: C(128x128 tile) = A(MxK,row-major) @ W^T (N x K, row-major)
// 256 threads, 8x8 per thread, k-tile = 16.
// ---------------------------------------------------------------------------
__device__ __forceinline__ void sgemm_core_128(
    const float* __restrict__ A, const float* __restrict__ W,
    int m0, int n0, float acc[8][8])
{
    __shared__ float As[16][128];
    __shared__ float Ws[16][128];
    const int tid = threadIdx.x;
    const int ty = tid >> 4;        // 0..15
    const int tx = tid & 15;        // 0..15
    const int lr = tid >> 2;        // 0..63
    const int lc = (tid & 3) << 2;  // 0,4,8,12

    const float* Ap = A + (size_t)(m0 + lr) * EMB + lc;
    const float* Wp = W + (size_t)(n0 + lr) * EMB + lc;

    for (int kt = 0; kt < EMB; kt += 16) {
        float4 a0 = *(const float4*)(Ap + kt);
        float4 a1 = *(const float4*)(Ap + kt + 64 * EMB);
        float4 w0 = *(const float4*)(Wp + kt);
        float4 w1 = *(const float4*)(Wp + kt + 64 * EMB);
        __syncthreads();
        As[lc + 0][lr] = a0.x; As[lc + 1][lr] = a0.y; As[lc + 2][lr] = a0.z; As[lc + 3][lr] = a0.w;
        As[lc + 0][lr + 64] = a1.x; As[lc + 1][lr + 64] = a1.y; As[lc + 2][lr + 64] = a1.z; As[lc + 3][lr + 64] = a1.w;
        Ws[lc + 0][lr] = w0.x; Ws[lc + 1][lr] = w0.y; Ws[lc + 2][lr] = w0.z; Ws[lc + 3][lr] = w0.w;
        Ws[lc + 0][lr + 64] = w1.x; Ws[lc + 1][lr + 64] = w1.y; Ws[lc + 2][lr + 64] = w1.z; Ws[lc + 3][lr + 64] = w1.w;
        __syncthreads();
        #pragma unroll
        for (int kk = 0; kk < 16; kk++) {
            float a[8], b[8];
            *(float4*)&a[0] = *(const float4*)&As[kk][ty * 8];
            *(float4*)&a[4] = *(const float4*)&As[kk][ty * 8 + 4];
            *(float4*)&b[0] = *(const float4*)&Ws[kk][tx * 8];
            *(float4*)&b[4] = *(const float4*)&Ws[kk][tx * 8 + 4];
            #pragma unroll
            for (int i = 0; i < 8; i++)
                #pragma unroll
                for (int j = 0; j < 8; j++)
                    acc[i][j] = fmaf(a[i], b[j], acc[i][j]);
        }
    }
}

// ---------------------------------------------------------------------------
// QKV projection: z selects (Wq,bq)->g_q, (Wk,bk)->g_k, (Wv,bv)->g_v.
// Output written head-split: dst[((b*NH+h)*SEQ+i)*HD + d]
// ---------------------------------------------------------------------------
__global__ __launch_bounds__(256) void qkv_kernel(
    const float* __restrict__ x,
    const float* __restrict__ Wq, const float* __restrict__ bq,
    const float* __restrict__ Wk, const float* __restrict__ bk,
    const float* __restrict__ Wv, const float* __restrict__ bv)
{
    const int z = blockIdx.z;
    const float* W    = (z == 0) ? Wq : (z == 1) ? Wk : Wv;
    const float* bias = (z == 0) ? bq : (z == 1) ? bk : bv;
    float* dst        = (z == 0) ? g_q : (z == 1) ? g_k : g_v;

    const int m0 = blockIdx.y * 128;
    const int n0 = blockIdx.x * 128;

    float acc[8][8];
    #pragma unroll
    for (int i = 0; i < 8; i++)
        #pragma unroll
        for (int j = 0; j < 8; j++) acc[i][j] = 0.f;

    sgemm_core_128(x, W, m0, n0, acc);

    const int ty = threadIdx.x >> 4;
    const int tx = threadIdx.x & 15;
    #pragma unroll
    for (int ii = 0; ii < 8; ii++) {
        const int m = m0 + ty * 8 + ii;
        const int b = m >> 11;       // / SEQ
        const int i = m & (SEQ - 1);
        #pragma unroll
        for (int jj = 0; jj < 8; jj += 4) {
            const int o = n0 + tx * 8 + jj;
            const int h = o >> 6;
            const int d = o & (HD - 1);
            float4 v;
            v.x = acc[ii][jj + 0] + __ldg(&bias[o + 0]);
            v.y = acc[ii][jj + 1] + __ldg(&bias[o + 1]);
            v.z = acc[ii][jj + 2] + __ldg(&bias[o + 2]);
            v.w = acc[ii][jj + 3] + __ldg(&bias[o + 3]);
            *(float4*)&dst[(((size_t)(b * NH + h) * SEQ + i) * HD) + d] = v;
        }
    }
}

// ---------------------------------------------------------------------------
// Fused flash attention + edge MLP.
// Grid: (SEQ/64, NH, BATCH). Block: 256 (16x16 -> 4x4 fragment).
// Smem: Qt[d][i], KtPs (K tile [d][j], reused as P[i][j]), Vs[j][d] = 48KB.
// ---------------------------------------------------------------------------
__global__ __launch_bounds__(256, 2) void attn_kernel(
    const float* __restrict__ adj,
    const float* __restrict__ We1, const float* __restrict__ be1,
    const float* __restrict__ We2, const float* __restrict__ be2,
    const float* __restrict__ ebias)
{
    __shared__ float Qt[64][64];    // [d][i]
    __shared__ float KtPs[64][64];  // K: [d][j]  then P: [i][j]
    __shared__ float Vs[64][64];    // [j][d]

    const int i0 = blockIdx.x * 64;
    const int h  = blockIdx.y;
    const int b  = blockIdx.z;
    const int tid = threadIdx.x;
    const int ty = tid >> 4;   // row group 0..15
    const int tx = tid & 15;   // col group 0..15

    const float* qbase = g_q + (size_t)(b * NH + h) * SEQ * HD;
    const float* kbase = g_k + (size_t)(b * NH + h) * SEQ * HD;
    const float* vbase = g_v + (size_t)(b * NH + h) * SEQ * HD;
    const float* abase = adj + (size_t)b * SEQ * SEQ;

    // Edge-MLP weights in registers (fully unrolled access only)
    float w1[EDIM], b1[EDIM], w2[EDIM];
    #pragma unroll
    for (int e = 0; e < EDIM; e++) {
        w1[e] = __ldg(&We1[e]);
        b1[e] = __ldg(&be1[e]);
        w2[e] = __ldg(&We2[h * EDIM + e]);
    }
    const float c2 = __ldg(&be2[h]);
    const float eb = __ldg(&ebias[h]);

    // Stage Q transposed: Qt[d][i]
    {
        const int li = tid >> 2;
        const int lc = (tid & 3) << 2;
        #pragma unroll
        for (int r = 0; r < 4; r++) {
            const int c = lc + r * 16;
            float4 q4 = *(const float4*)&qbase[(size_t)(i0 + li) * HD + c];
            Qt[c + 0][li] = q4.x; Qt[c + 1][li] = q4.y;
            Qt[c + 2][li] = q4.z; Qt[c + 3][li] = q4.w;
        }
    }

    float O[4][4];
    float m_r[4], l_r[4];
    #pragma unroll
    for (int ii = 0; ii < 4; ii++) {
        m_r[ii] = -3.0e38f; l_r[ii] = 0.f;
        #pragma unroll
        for (int jj = 0; jj < 4; jj++) O[ii][jj] = 0.f;
    }

    const float scale = 0.125f;  // 1/sqrt(64)

    for (int jt = 0; jt < SEQ / 64; jt++) {
        const int j0 = jt * 64;
        __syncthreads();  // previous PV reads done (KtPs as P, Vs)

        // Stage K transposed + V direct
        {
            const int li = tid >> 2;
            const int lc = (tid & 3) << 2;
            #pragma unroll
            for (int r = 0; r < 4; r++) {
                const int c = lc + r * 16;
                float4 k4 = *(const float4*)&kbase[(size_t)(j0 + li) * HD + c];
                KtPs[c + 0][li] = k4.x; KtPs[c + 1][li] = k4.y;
                KtPs[c + 2][li] = k4.z; KtPs[c + 3][li] = k4.w;
            }
            #pragma unroll
            for (int r = 0; r < 4; r++) {
                const int f  = r * 256 + tid;     // float4 index
                const int j  = f >> 4;
                const int d4 = (f & 15) << 2;
                *(float4*)&Vs[j][d4] = *(const float4*)&vbase[(size_t)(j0 + j) * HD + d4];
            }
        }
        __syncthreads();

        // S = Q K^T (rank-1 over d)
        float S[4][4];
        #pragma unroll
        for (int ii = 0; ii < 4; ii++)
            #pragma unroll
            for (int jj = 0; jj < 4; jj++) S[ii][jj] = 0.f;

        #pragma unroll 16
        for (int d = 0; d < 64; d++) {
            float4 a4 = *(const float4*)&Qt[d][ty * 4];
            float4 b4 = *(const float4*)&KtPs[d][tx * 4];
            float av[4] = {a4.x, a4.y, a4.z, a4.w};
            float bv[4] = {b4.x, b4.y, b4.z, b4.w};
            #pragma unroll
            for (int ii = 0; ii < 4; ii++)
                #pragma unroll
                for (int jj = 0; jj < 4; jj++)
                    S[ii][jj] = fmaf(av[ii], bv[jj], S[ii][jj]);
        }

        // adjacency fragment (global, L2-resident) + scale + edge MLP + boost
        float a[4][4];
        #pragma unroll
        for (int ii = 0; ii < 4; ii++) {
            float4 av = __ldg((const float4*)&abase[(size_t)(i0 + ty * 4 + ii) * SEQ + j0 + tx * 4]);
            a[ii][0] = av.x; a[ii][1] = av.y; a[ii][2] = av.z; a[ii][3] = av.w;
        }
        #pragma unroll
        for (int ii = 0; ii < 4; ii++)
            #pragma unroll
            for (int jj = 0; jj < 4; jj++)
                S[ii][jj] = fmaf(S[ii][jj], scale, fmaf(a[ii][jj], eb, c2));
        #pragma unroll
        for (int e = 0; e < EDIM; e++) {
            #pragma unroll
            for (int ii = 0; ii < 4; ii++)
                #pragma unroll
                for (int jj = 0; jj < 4; jj++) {
                    float t = fmaf(a[ii][jj], w1[e], b1[e]);
                    t = fmaxf(t, 0.f);
                    S[ii][jj] = fmaf(t, w2[e], S[ii][jj]);
                }
        }

        // Online softmax (rows distributed over the 16 tx lanes of a half-warp)
        float mt[4];
        #pragma unroll
        for (int ii = 0; ii < 4; ii++)
            mt[ii] = fmaxf(fmaxf(S[ii][0], S[ii][1]), fmaxf(S[ii][2], S[ii][3]));
        #pragma unroll
        for (int off = 1; off < 16; off <<= 1) {
            #pragma unroll
            for (int ii = 0; ii < 4; ii++)
                mt[ii] = fmaxf(mt[ii], __shfl_xor_sync(0xffffffffu, mt[ii], off));
        }

        float corr[4], rs[4];
        #pragma unroll
        for (int ii = 0; ii < 4; ii++) {
            float mn = fmaxf(m_r[ii], mt[ii]);
            corr[ii] = __expf(m_r[ii] - mn);
            m_r[ii] = mn;
            float s = 0.f;
            #pragma unroll
            for (int jj = 0; jj < 4; jj++) {
                S[ii][jj] = __expf(S[ii][jj] - mn);
                s += S[ii][jj];
            }
            rs[ii] = s;
        }
        #pragma unroll
        for (int off = 1; off < 16; off <<= 1) {
            #pragma unroll
            for (int ii = 0; ii < 4; ii++)
                rs[ii] += __shfl_xor_sync(0xffffffffu, rs[ii], off);
        }
        #pragma unroll
        for (int ii = 0; ii < 4; ii++) {
            l_r[ii] = l_r[ii] * corr[ii] + rs[ii];
            #pragma unroll
            for (int jj = 0; jj < 4; jj++) O[ii][jj] *= corr[ii];
        }

        __syncthreads();  // all threads finished reading KtPs as K
        // Store P[i][j] over the K tile
        #pragma unroll
        for (int ii = 0; ii < 4; ii++) {
            float4 p4 = make_float4(S[ii][0], S[ii][1], S[ii][2], S[ii][3]);
            *(float4*)&KtPs[ty * 4 + ii][tx * 4] = p4;
        }
        __syncthreads();

        // O += P @ V  (rank-1 over j)
        #pragma unroll 8
        for (int j = 0; j < 64; j++) {
            float4 v4 = *(const float4*)&Vs[j][tx * 4];
            float p0 = KtPs[ty * 4 + 0][j];
            float p1 = KtPs[ty * 4 + 1][j];
            float p2 = KtPs[ty * 4 + 2][j];
            float p3 = KtPs[ty * 4 + 3][j];
            O[0][0] = fmaf(p0, v4.x, O[0][0]); O[0][1] = fmaf(p0, v4.y, O[0][1]);
            O[0][2] = fmaf(p0, v4.z, O[0][2]); O[0][3] = fmaf(p0, v4.w, O[0][3]);
            O[1][0] = fmaf(p1, v4.x, O[1][0]); O[1][1] = fmaf(p1, v4.y, O[1][1]);
            O[1][2] = fmaf(p1, v4.z, O[1][2]); O[1][3] = fmaf(p1, v4.w, O[1][3]);
            O[2][0] = fmaf(p2, v4.x, O[2][0]); O[2][1] = fmaf(p2, v4.y, O[2][1]);
            O[2][2] = fmaf(p2, v4.z, O[2][2]); O[2][3] = fmaf(p2, v4.w, O[2][3]);
            O[3][0] = fmaf(p3, v4.x, O[3][0]); O[3][1] = fmaf(p3, v4.y, O[3][1]);
            O[3][2] = fmaf(p3, v4.z, O[3][2]); O[3][3] = fmaf(p3, v4.w, O[3][3]);
        }
    }

    // Epilogue: normalize and write to g_ao in (b, n, E) layout
    float* obase = g_ao + (size_t)(b * SEQ + i0) * EMB + h * HD;
    #pragma unroll
    for (int ii = 0; ii < 4; ii++) {
        const float inv = 1.f / l_r[ii];
        float4 o4 = make_float4(O[ii][0] * inv, O[ii][1] * inv,
                                O[ii][2] * inv, O[ii][3] * inv);
        *(float4*)&obase[(size_t)(ty * 4 + ii) * EMB + tx * 4] = o4;
    }
}

// ---------------------------------------------------------------------------
// Output projection: out = g_ao @ Wo^T + bo (row-major out)
// ---------------------------------------------------------------------------
__global__ __launch_bounds__(256) void oproj_kernel(
    const float* __restrict__ Wo, const float* __restrict__ bo,
    float* __restrict__ out)
{
    const int m0 = blockIdx.y * 128;
    const int n0 = blockIdx.x * 128;

    float acc[8][8];
    #pragma unroll
    for (int i = 0; i < 8; i++)
        #pragma unroll
        for (int j = 0; j < 8; j++) acc[i][j] = 0.f;

    sgemm_core_128(g_ao, Wo, m0, n0, acc);

    const int ty = threadIdx.x >> 4;
    const int tx = threadIdx.x & 15;
    #pragma unroll
    for (int ii = 0; ii < 8; ii++) {
        const int m = m0 + ty * 8 + ii;
        #pragma unroll
        for (int jj = 0; jj < 8; jj += 4) {
            const int o = n0 + tx * 8 + jj;
            float4 v;
            v.x = acc[ii][jj + 0] + __ldg(&bo[o + 0]);
            v.y = acc[ii][jj + 1] + __ldg(&bo[o + 1]);
            v.z = acc[ii][jj + 2] + __ldg(&bo[o + 2]);
            v.w = acc[ii][jj + 3] + __ldg(&bo[o + 3]);
            *(float4*)&out[(size_t)m * EMB + o] = v;
        }
    }
}

// ---------------------------------------------------------------------------
extern "C" void kernel_launch(void* const* d_in, const int* in_sizes, int n_in,
                              void* d_out, int out_size)
{
    const float* x   = (const float*)d_in[0];
    const float* adj = (const float*)d_in[1];
    const float* Wq  = (const float*)d_in[2];
    const float* bq  = (const float*)d_in[3];
    const float* Wk  = (const float*)d_in[4];
    const float* bk  = (const float*)d_in[5];
    const float* Wv  = (const float*)d_in[6];
    const float* bv  = (const float*)d_in[7];
    const float* Wo  = (const float*)d_in[8];
    const float* bo  = (const float*)d_in[9];
    const float* We1 = (const float*)d_in[10];
    const float* be1 = (const float*)d_in[11];
    const float* We2 = (const float*)d_in[12];
    const float* be2 = (const float*)d_in[13];
    const float* eb  = (const float*)d_in[14];
    float* out = (float*)d_out;

    qkv_kernel<<<dim3(EMB / 128, MROWS / 128, 3), 256>>>(x, Wq, bq, Wk, bk, Wv, bv);
    attn_kernel<<<dim3(SEQ / 64, NH, BATCH), 256>>>(adj, We1, be1, We2, be2, eb);
    oproj_kernel<<<dim3(EMB / 128, MROWS / 128), 256>>>(Wo, bo, out);
}

// round 3
// speedup vs baseline: 1.4835x; 1.4835x over previous
#include <cuda_runtime.h>

#define BATCH 2
#define SEQ   2048
#define NH    8
#define HD    64
#define EMB   512
#define EDIM  16
#define MROWS (BATCH*SEQ)   // 4096

// Scratch (no cudaMalloc allowed): 4 x 8MB
__device__ float g_q[BATCH*NH*SEQ*HD];
__device__ float g_k[BATCH*NH*SEQ*HD];
__device__ float g_v[BATCH*NH*SEQ*HD];
__device__ float g_ao[MROWS*EMB];

// ---------------------------------------------------------------------------
// tf32 helpers
// ---------------------------------------------------------------------------
__device__ __forceinline__ unsigned f2t(float x) {
    unsigned u;
    asm("cvt.rna.tf32.f32 %0, %1;" : "=r"(u) : "f"(x));
    return u;
}

__device__ __forceinline__ void mma8(float& d0, float& d1, float& d2, float& d3,
                                     unsigned a0, unsigned a1, unsigned a2, unsigned a3,
                                     unsigned b0, unsigned b1)
{
    asm volatile(
        "mma.sync.aligned.m16n8k8.row.col.f32.tf32.tf32.f32 "
        "{%0,%1,%2,%3}, {%4,%5,%6,%7}, {%8,%9}, {%0,%1,%2,%3};"
        : "+f"(d0), "+f"(d1), "+f"(d2), "+f"(d3)
        : "r"(a0), "r"(a1), "r"(a2), "r"(a3), "r"(b0), "r"(b1));
}

// ---------------------------------------------------------------------------
// SGEMM core: C(128x128 tile) = A(MxK,row-major) @ W^T (N x K, row-major)
// 256 threads, 8x8 per thread, k-tile = 16. (proven in R1)
// ---------------------------------------------------------------------------
__device__ __forceinline__ void sgemm_core_128(
    const float* __restrict__ A, const float* __restrict__ W,
    int m0, int n0, float acc[8][8])
{
    __shared__ float As[16][128];
    __shared__ float Ws[16][128];
    const int tid = threadIdx.x;
    const int ty = tid >> 4;        // 0..15
    const int tx = tid & 15;        // 0..15
    const int lr = tid >> 2;        // 0..63
    const int lc = (tid & 3) << 2;  // 0,4,8,12

    const float* Ap = A + (size_t)(m0 + lr) * EMB + lc;
    const float* Wp = W + (size_t)(n0 + lr) * EMB + lc;

    for (int kt = 0; kt < EMB; kt += 16) {
        float4 a0 = *(const float4*)(Ap + kt);
        float4 a1 = *(const float4*)(Ap + kt + 64 * EMB);
        float4 w0 = *(const float4*)(Wp + kt);
        float4 w1 = *(const float4*)(Wp + kt + 64 * EMB);
        __syncthreads();
        As[lc + 0][lr] = a0.x; As[lc + 1][lr] = a0.y; As[lc + 2][lr] = a0.z; As[lc + 3][lr] = a0.w;
        As[lc + 0][lr + 64] = a1.x; As[lc + 1][lr + 64] = a1.y; As[lc + 2][lr + 64] = a1.z; As[lc + 3][lr + 64] = a1.w;
        Ws[lc + 0][lr] = w0.x; Ws[lc + 1][lr] = w0.y; Ws[lc + 2][lr] = w0.z; Ws[lc + 3][lr] = w0.w;
        Ws[lc + 0][lr + 64] = w1.x; Ws[lc + 1][lr + 64] = w1.y; Ws[lc + 2][lr + 64] = w1.z; Ws[lc + 3][lr + 64] = w1.w;
        __syncthreads();
        #pragma unroll
        for (int kk = 0; kk < 16; kk++) {
            float a[8], b[8];
            *(float4*)&a[0] = *(const float4*)&As[kk][ty * 8];
            *(float4*)&a[4] = *(const float4*)&As[kk][ty * 8 + 4];
            *(float4*)&b[0] = *(const float4*)&Ws[kk][tx * 8];
            *(float4*)&b[4] = *(const float4*)&Ws[kk][tx * 8 + 4];
            #pragma unroll
            for (int i = 0; i < 8; i++)
                #pragma unroll
                for (int j = 0; j < 8; j++)
                    acc[i][j] = fmaf(a[i], b[j], acc[i][j]);
        }
    }
}

// ---------------------------------------------------------------------------
// QKV projection: z selects (Wq,bq)->g_q, (Wk,bk)->g_k, (Wv,bv)->g_v.
// Output written head-split: dst[((b*NH+h)*SEQ+i)*HD + d]
// ---------------------------------------------------------------------------
__global__ __launch_bounds__(256) void qkv_kernel(
    const float* __restrict__ x,
    const float* __restrict__ Wq, const float* __restrict__ bq,
    const float* __restrict__ Wk, const float* __restrict__ bk,
    const float* __restrict__ Wv, const float* __restrict__ bv)
{
    const int z = blockIdx.z;
    const float* W    = (z == 0) ? Wq : (z == 1) ? Wk : Wv;
    const float* bias = (z == 0) ? bq : (z == 1) ? bk : bv;
    float* dst        = (z == 0) ? g_q : (z == 1) ? g_k : g_v;

    const int m0 = blockIdx.y * 128;
    const int n0 = blockIdx.x * 128;

    float acc[8][8];
    #pragma unroll
    for (int i = 0; i < 8; i++)
        #pragma unroll
        for (int j = 0; j < 8; j++) acc[i][j] = 0.f;

    sgemm_core_128(x, W, m0, n0, acc);

    const int ty = threadIdx.x >> 4;
    const int tx = threadIdx.x & 15;
    #pragma unroll
    for (int ii = 0; ii < 8; ii++) {
        const int m = m0 + ty * 8 + ii;
        const int b = m >> 11;       // / SEQ
        const int i = m & (SEQ - 1);
        #pragma unroll
        for (int jj = 0; jj < 8; jj += 4) {
            const int o = n0 + tx * 8 + jj;
            const int h = o >> 6;
            const int d = o & (HD - 1);
            float4 v;
            v.x = acc[ii][jj + 0] + __ldg(&bias[o + 0]);
            v.y = acc[ii][jj + 1] + __ldg(&bias[o + 1]);
            v.z = acc[ii][jj + 2] + __ldg(&bias[o + 2]);
            v.w = acc[ii][jj + 3] + __ldg(&bias[o + 3]);
            *(float4*)&dst[(((size_t)(b * NH + h) * SEQ + i) * HD) + d] = v;
        }
    }
}

// ---------------------------------------------------------------------------
// Fused flash attention + edge MLP, tf32 tensor cores.
// Grid: (NH, SEQ/64, BATCH). Block: 128 threads = 4 warps; warp w owns rows
// 16w..16w+15 of the 64-row i-tile. QK^T and PV are m16n8k8 tf32 mma.
// Smem (LDP=72): SA: K tile [j][d] (tf32), reused as P tile [i][j] (tf32)
//                SB: V tile [j][d] (tf32); also stages Q at kernel start.
// ---------------------------------------------------------------------------
__global__ __launch_bounds__(128, 2) void attn_kernel(
    const float* __restrict__ adj,
    const float* __restrict__ We1, const float* __restrict__ be1,
    const float* __restrict__ We2, const float* __restrict__ be2,
    const float* __restrict__ ebias)
{
    const int LDP = 72;
    __shared__ float SA[64 * 72];
    __shared__ float SB[64 * 72];
    __shared__ float ew1[EDIM], eb1[EDIM], ew2[EDIM];

    const int h   = blockIdx.x;
    const int i0  = blockIdx.y * 64;
    const int b   = blockIdx.z;
    const int tid = threadIdx.x;
    const int w   = tid >> 5;
    const int ln  = tid & 31;
    const int g   = ln >> 2;
    const int tg  = ln & 3;
    const int rl  = 16 * w + g;        // local row (0..63); this thread covers rl and rl+8

    const float* qbase = g_q + (size_t)(b * NH + h) * SEQ * HD;
    const float* kbase = g_k + (size_t)(b * NH + h) * SEQ * HD;
    const float* vbase = g_v + (size_t)(b * NH + h) * SEQ * HD;
    const float* abase = adj + (size_t)b * SEQ * SEQ;

    if (tid < EDIM) {
        ew1[tid] = We1[tid];
        eb1[tid] = be1[tid];
        ew2[tid] = We2[h * EDIM + tid];
    }
    const float c2 = __ldg(&be2[h]);
    const float eb = __ldg(&ebias[h]);

    // ---- Stage Q (tf32) into SA: 64 rows x 16 float4 = 1024 float4 ----
    #pragma unroll
    for (int p = 0; p < 8; p++) {
        const int idx = p * 128 + tid;
        const int row = idx >> 4;
        const int c4  = (idx & 15) << 2;
        float4 v = *(const float4*)&qbase[(size_t)(i0 + row) * HD + c4];
        *(uint4*)&SA[row * LDP + c4] = make_uint4(f2t(v.x), f2t(v.y), f2t(v.z), f2t(v.w));
    }
    __syncthreads();

    unsigned Qf[8][4];
    #pragma unroll
    for (int k0 = 0; k0 < 8; k0++) {
        Qf[k0][0] = __float_as_uint(SA[(rl    ) * LDP + 8 * k0 + tg    ]);
        Qf[k0][1] = __float_as_uint(SA[(rl + 8) * LDP + 8 * k0 + tg    ]);
        Qf[k0][2] = __float_as_uint(SA[(rl    ) * LDP + 8 * k0 + tg + 4]);
        Qf[k0][3] = __float_as_uint(SA[(rl + 8) * LDP + 8 * k0 + tg + 4]);
    }

    float O[8][4];
    #pragma unroll
    for (int nt = 0; nt < 8; nt++)
        #pragma unroll
        for (int c = 0; c < 4; c++) O[nt][c] = 0.f;
    float m0 = -3.0e38f, m1 = -3.0e38f, l0 = 0.f, l1 = 0.f;
    const float scale = 0.125f;  // 1/sqrt(64)

    for (int jt = 0; jt < SEQ / 64; jt++) {
        const int j0 = jt * 64;
        __syncthreads();  // previous iter's P/V reads complete (also guards Qf vs K overwrite)

        // ---- stage K, V (tf32): full 64x64 tiles ----
        #pragma unroll
        for (int p = 0; p < 8; p++) {
            const int idx = p * 128 + tid;
            const int row = idx >> 4;
            const int c4  = (idx & 15) << 2;
            float4 kv = *(const float4*)&kbase[(size_t)(j0 + row) * HD + c4];
            *(uint4*)&SA[row * LDP + c4] = make_uint4(f2t(kv.x), f2t(kv.y), f2t(kv.z), f2t(kv.w));
            float4 vv = *(const float4*)&vbase[(size_t)(j0 + row) * HD + c4];
            *(uint4*)&SB[row * LDP + c4] = make_uint4(f2t(vv.x), f2t(vv.y), f2t(vv.z), f2t(vv.w));
        }
        __syncthreads();

        // ---- prefetch adjacency fragment (overlaps with mma) ----
        float2 aL[8], aH[8];
        #pragma unroll
        for (int nt = 0; nt < 8; nt++) {
            const int col = j0 + 8 * nt + 2 * tg;
            aL[nt] = __ldg((const float2*)&abase[(size_t)(i0 + rl    ) * SEQ + col]);
            aH[nt] = __ldg((const float2*)&abase[(size_t)(i0 + rl + 8) * SEQ + col]);
        }

        // ---- S = Q K^T (tf32 mma) ----
        float S[8][4];
        #pragma unroll
        for (int nt = 0; nt < 8; nt++)
            #pragma unroll
            for (int c = 0; c < 4; c++) S[nt][c] = 0.f;

        #pragma unroll
        for (int k0 = 0; k0 < 8; k0++) {
            #pragma unroll
            for (int nt = 0; nt < 8; nt++) {
                unsigned b0 = __float_as_uint(SA[(8 * nt + g) * LDP + 8 * k0 + tg    ]);
                unsigned b1 = __float_as_uint(SA[(8 * nt + g) * LDP + 8 * k0 + tg + 4]);
                mma8(S[nt][0], S[nt][1], S[nt][2], S[nt][3],
                     Qf[k0][0], Qf[k0][1], Qf[k0][2], Qf[k0][3], b0, b1);
            }
        }
        __syncthreads();  // all warps done reading K; SA now free for P

        // ---- scale + edge bias + boost ----
        #pragma unroll
        for (int nt = 0; nt < 8; nt++) {
            S[nt][0] = fmaf(S[nt][0], scale, fmaf(aL[nt].x, eb, c2));
            S[nt][1] = fmaf(S[nt][1], scale, fmaf(aL[nt].y, eb, c2));
            S[nt][2] = fmaf(S[nt][2], scale, fmaf(aH[nt].x, eb, c2));
            S[nt][3] = fmaf(S[nt][3], scale, fmaf(aH[nt].y, eb, c2));
        }
        // ---- edge MLP (non-unrolled e-loop, weights broadcast from smem) ----
        #pragma unroll 1
        for (int e = 0; e < EDIM; e++) {
            const float w1e = ew1[e], b1e = eb1[e], w2e = ew2[e];
            #pragma unroll
            for (int nt = 0; nt < 8; nt++) {
                S[nt][0] = fmaf(fmaxf(fmaf(aL[nt].x, w1e, b1e), 0.f), w2e, S[nt][0]);
                S[nt][1] = fmaf(fmaxf(fmaf(aL[nt].y, w1e, b1e), 0.f), w2e, S[nt][1]);
                S[nt][2] = fmaf(fmaxf(fmaf(aH[nt].x, w1e, b1e), 0.f), w2e, S[nt][2]);
                S[nt][3] = fmaf(fmaxf(fmaf(aH[nt].y, w1e, b1e), 0.f), w2e, S[nt][3]);
            }
        }

        // ---- online softmax (rows rl and rl+8, quad reduction) ----
        float mt0 = -3.0e38f, mt1 = -3.0e38f;
        #pragma unroll
        for (int nt = 0; nt < 8; nt++) {
            mt0 = fmaxf(mt0, fmaxf(S[nt][0], S[nt][1]));
            mt1 = fmaxf(mt1, fmaxf(S[nt][2], S[nt][3]));
        }
        mt0 = fmaxf(mt0, __shfl_xor_sync(0xffffffffu, mt0, 1));
        mt0 = fmaxf(mt0, __shfl_xor_sync(0xffffffffu, mt0, 2));
        mt1 = fmaxf(mt1, __shfl_xor_sync(0xffffffffu, mt1, 1));
        mt1 = fmaxf(mt1, __shfl_xor_sync(0xffffffffu, mt1, 2));

        const float mn0 = fmaxf(m0, mt0);
        const float mn1 = fmaxf(m1, mt1);
        const float cr0 = __expf(m0 - mn0);
        const float cr1 = __expf(m1 - mn1);
        m0 = mn0; m1 = mn1;

        float rs0 = 0.f, rs1 = 0.f;
        #pragma unroll
        for (int nt = 0; nt < 8; nt++) {
            S[nt][0] = __expf(S[nt][0] - mn0);
            S[nt][1] = __expf(S[nt][1] - mn0);
            S[nt][2] = __expf(S[nt][2] - mn1);
            S[nt][3] = __expf(S[nt][3] - mn1);
            rs0 += S[nt][0] + S[nt][1];
            rs1 += S[nt][2] + S[nt][3];
        }
        rs0 += __shfl_xor_sync(0xffffffffu, rs0, 1);
        rs0 += __shfl_xor_sync(0xffffffffu, rs0, 2);
        rs1 += __shfl_xor_sync(0xffffffffu, rs1, 1);
        rs1 += __shfl_xor_sync(0xffffffffu, rs1, 2);
        l0 = l0 * cr0 + rs0;
        l1 = l1 * cr1 + rs1;

        #pragma unroll
        for (int nt = 0; nt < 8; nt++) {
            O[nt][0] *= cr0; O[nt][1] *= cr0;
            O[nt][2] *= cr1; O[nt][3] *= cr1;
        }

        // ---- store P (tf32) into SA (own warp's rows only) ----
        #pragma unroll
        for (int nt = 0; nt < 8; nt++) {
            *(float2*)&SA[(rl    ) * LDP + 8 * nt + 2 * tg] =
                make_float2(__uint_as_float(f2t(S[nt][0])), __uint_as_float(f2t(S[nt][1])));
            *(float2*)&SA[(rl + 8) * LDP + 8 * nt + 2 * tg] =
                make_float2(__uint_as_float(f2t(S[nt][2])), __uint_as_float(f2t(S[nt][3])));
        }
        __syncwarp();  // A-frags below read only this warp's rows

        // ---- O += P V (tf32 mma) ----
        #pragma unroll
        for (int k0 = 0; k0 < 8; k0++) {
            unsigned pa0 = __float_as_uint(SA[(rl    ) * LDP + 8 * k0 + tg    ]);
            unsigned pa1 = __float_as_uint(SA[(rl + 8) * LDP + 8 * k0 + tg    ]);
            unsigned pa2 = __float_as_uint(SA[(rl    ) * LDP + 8 * k0 + tg + 4]);
            unsigned pa3 = __float_as_uint(SA[(rl + 8) * LDP + 8 * k0 + tg + 4]);
            #pragma unroll
            for (int nt = 0; nt < 8; nt++) {
                unsigned b0 = __float_as_uint(SB[(8 * k0 + tg    ) * LDP + 8 * nt + g]);
                unsigned b1 = __float_as_uint(SB[(8 * k0 + tg + 4) * LDP + 8 * nt + g]);
                mma8(O[nt][0], O[nt][1], O[nt][2], O[nt][3], pa0, pa1, pa2, pa3, b0, b1);
            }
        }
    }

    // ---- epilogue: normalize, write (b, n, E) layout ----
    const float iv0 = 1.f / l0;
    const float iv1 = 1.f / l1;
    float* ob = g_ao + (size_t)(b * SEQ + i0 + rl) * EMB + h * HD;
    #pragma unroll
    for (int nt = 0; nt < 8; nt++) {
        *(float2*)&ob[8 * nt + 2 * tg] = make_float2(O[nt][0] * iv0, O[nt][1] * iv0);
        *(float2*)&ob[(size_t)8 * EMB + 8 * nt + 2 * tg] = make_float2(O[nt][2] * iv1, O[nt][3] * iv1);
    }
}

// ---------------------------------------------------------------------------
// Output projection: out = g_ao @ Wo^T + bo (row-major out)
// ---------------------------------------------------------------------------
__global__ __launch_bounds__(256) void oproj_kernel(
    const float* __restrict__ Wo, const float* __restrict__ bo,
    float* __restrict__ out)
{
    const int m0 = blockIdx.y * 128;
    const int n0 = blockIdx.x * 128;

    float acc[8][8];
    #pragma unroll
    for (int i = 0; i < 8; i++)
        #pragma unroll
        for (int j = 0; j < 8; j++) acc[i][j] = 0.f;

    sgemm_core_128(g_ao, Wo, m0, n0, acc);

    const int ty = threadIdx.x >> 4;
    const int tx = threadIdx.x & 15;
    #pragma unroll
    for (int ii = 0; ii < 8; ii++) {
        const int m = m0 + ty * 8 + ii;
        #pragma unroll
        for (int jj = 0; jj < 8; jj += 4) {
            const int o = n0 + tx * 8 + jj;
            float4 v;
            v.x = acc[ii][jj + 0] + __ldg(&bo[o + 0]);
            v.y = acc[ii][jj + 1] + __ldg(&bo[o + 1]);
            v.z = acc[ii][jj + 2] + __ldg(&bo[o + 2]);
            v.w = acc[ii][jj + 3] + __ldg(&bo[o + 3]);
            *(float4*)&out[(size_t)m * EMB + o] = v;
        }
    }
}

// ---------------------------------------------------------------------------
extern "C" void kernel_launch(void* const* d_in, const int* in_sizes, int n_in,
                              void* d_out, int out_size)
{
    const float* x   = (const float*)d_in[0];
    const float* adj = (const float*)d_in[1];
    const float* Wq  = (const float*)d_in[2];
    const float* bq  = (const float*)d_in[3];
    const float* Wk  = (const float*)d_in[4];
    const float* bk  = (const float*)d_in[5];
    const float* Wv  = (const float*)d_in[6];
    const float* bv  = (const float*)d_in[7];
    const float* Wo  = (const float*)d_in[8];
    const float* bo  = (const float*)d_in[9];
    const float* We1 = (const float*)d_in[10];
    const float* be1 = (const float*)d_in[11];
    const float* We2 = (const float*)d_in[12];
    const float* be2 = (const float*)d_in[13];
    const float* eb  = (const float*)d_in[14];
    float* out = (float*)d_out;

    qkv_kernel<<<dim3(EMB / 128, MROWS / 128, 3), 256>>>(x, Wq, bq, Wk, bk, Wv, bv);
    attn_kernel<<<dim3(NH, SEQ / 64, BATCH), 128>>>(adj, We1, be1, We2, be2, eb);
    oproj_kernel<<<dim3(EMB / 128, MROWS / 128), 256>>>(Wo, bo, out);
}

// round 4
// speedup vs baseline: 1.9629x; 1.3231x over previous
#include <cuda_runtime.h>

#define BATCH 2
#define SEQ   2048
#define NH    8
#define HD    64
#define EMB   512
#define EDIM  16
#define MROWS (BATCH*SEQ)   // 4096

// Scratch (no cudaMalloc allowed): 4 x 8MB
__device__ float g_q[BATCH*NH*SEQ*HD];
__device__ float g_k[BATCH*NH*SEQ*HD];
__device__ float g_v[BATCH*NH*SEQ*HD];
__device__ float g_ao[MROWS*EMB];

// ---------------------------------------------------------------------------
// tf32 helpers
// ---------------------------------------------------------------------------
__device__ __forceinline__ unsigned f2t(float x) {
    unsigned u;
    asm("cvt.rna.tf32.f32 %0, %1;" : "=r"(u) : "f"(x));
    return u;
}

__device__ __forceinline__ void mma8(float& d0, float& d1, float& d2, float& d3,
                                     unsigned a0, unsigned a1, unsigned a2, unsigned a3,
                                     unsigned b0, unsigned b1)
{
    asm volatile(
        "mma.sync.aligned.m16n8k8.row.col.f32.tf32.tf32.f32 "
        "{%0,%1,%2,%3}, {%4,%5,%6,%7}, {%8,%9}, {%0,%1,%2,%3};"
        : "+f"(d0), "+f"(d1), "+f"(d2), "+f"(d3)
        : "r"(a0), "r"(a1), "r"(a2), "r"(a3), "r"(b0), "r"(b1));
}

// ---------------------------------------------------------------------------
// tf32 GEMM core: C(128x128 tile) = A(Mx512 row-major) @ W^T (512x512, W is
// (out,in) row-major so W[n][k]). 256 thr = 8 warps (4 m x 2 n); each warp
// computes 32x64 = 2 m-frags x 8 n-frags of m16n8k8. BK=32 (4 k-steps/chunk).
// c[mf][nf][0..3]: rows (wm+16mf+g, +8), cols (wn+8nf+2tg, +1).
// ---------------------------------------------------------------------------
__device__ __forceinline__ void gemm_tf32_core(
    const float* __restrict__ A, const float* __restrict__ W,
    int m0, int n0, float c[2][8][4])
{
    const int LDP = 36;
    __shared__ float As[128 * 36];
    __shared__ float Ws[128 * 36];

    const int tid = threadIdx.x;
    const int w  = tid >> 5;
    const int ln = tid & 31;
    const int g  = ln >> 2;
    const int tg = ln & 3;
    const int wm = (w & 3) * 32;
    const int wn = (w >> 2) * 64;

    // staging map: two threads per row, 4 float4 (16 floats) each
    const int srow = tid >> 1;
    const int scol = (tid & 1) * 16;

    const float* Ap = A + (size_t)(m0 + srow) * EMB + scol;
    const float* Wp = W + (size_t)(n0 + srow) * EMB + scol;

    for (int kt = 0; kt < EMB; kt += 32) {
        float4 av[4], wv[4];
        #pragma unroll
        for (int q = 0; q < 4; q++) {
            av[q] = *(const float4*)(Ap + kt + 4 * q);
            wv[q] = *(const float4*)(Wp + kt + 4 * q);
        }
        __syncthreads();   // previous chunk's compute done
        #pragma unroll
        for (int q = 0; q < 4; q++) {
            *(uint4*)&As[srow * LDP + scol + 4 * q] =
                make_uint4(f2t(av[q].x), f2t(av[q].y), f2t(av[q].z), f2t(av[q].w));
            *(uint4*)&Ws[srow * LDP + scol + 4 * q] =
                make_uint4(f2t(wv[q].x), f2t(wv[q].y), f2t(wv[q].z), f2t(wv[q].w));
        }
        __syncthreads();

        #pragma unroll
        for (int ks = 0; ks < 4; ks++) {
            const int kb = ks * 8;
            unsigned af[2][4];
            #pragma unroll
            for (int mf = 0; mf < 2; mf++) {
                const int r = wm + 16 * mf + g;
                af[mf][0] = __float_as_uint(As[(r    ) * LDP + kb + tg    ]);
                af[mf][1] = __float_as_uint(As[(r + 8) * LDP + kb + tg    ]);
                af[mf][2] = __float_as_uint(As[(r    ) * LDP + kb + tg + 4]);
                af[mf][3] = __float_as_uint(As[(r + 8) * LDP + kb + tg + 4]);
            }
            #pragma unroll
            for (int nf = 0; nf < 8; nf++) {
                const int nr = wn + 8 * nf + g;
                unsigned b0 = __float_as_uint(Ws[nr * LDP + kb + tg    ]);
                unsigned b1 = __float_as_uint(Ws[nr * LDP + kb + tg + 4]);
                mma8(c[0][nf][0], c[0][nf][1], c[0][nf][2], c[0][nf][3],
                     af[0][0], af[0][1], af[0][2], af[0][3], b0, b1);
                mma8(c[1][nf][0], c[1][nf][1], c[1][nf][2], c[1][nf][3],
                     af[1][0], af[1][1], af[1][2], af[1][3], b0, b1);
            }
        }
    }
}

// ---------------------------------------------------------------------------
// QKV projection (tf32 mma): z selects weight/bias/dst.
// Output head-split: dst[((b*NH+h)*SEQ+i)*HD + d]
// ---------------------------------------------------------------------------
__global__ __launch_bounds__(256, 2) void qkv_kernel(
    const float* __restrict__ x,
    const float* __restrict__ Wq, const float* __restrict__ bq,
    const float* __restrict__ Wk, const float* __restrict__ bk,
    const float* __restrict__ Wv, const float* __restrict__ bv)
{
    const int z = blockIdx.z;
    const float* W    = (z == 0) ? Wq : (z == 1) ? Wk : Wv;
    const float* bias = (z == 0) ? bq : (z == 1) ? bk : bv;
    float* dst        = (z == 0) ? g_q : (z == 1) ? g_k : g_v;

    const int m0 = blockIdx.y * 128;
    const int n0 = blockIdx.x * 128;

    float c[2][8][4];
    #pragma unroll
    for (int mf = 0; mf < 2; mf++)
        #pragma unroll
        for (int nf = 0; nf < 8; nf++)
            #pragma unroll
            for (int q = 0; q < 4; q++) c[mf][nf][q] = 0.f;

    gemm_tf32_core(x, W, m0, n0, c);

    const int ln = threadIdx.x & 31;
    const int g  = ln >> 2;
    const int tg = ln & 3;
    const int wm = ((threadIdx.x >> 5) & 3) * 32;
    const int wn = (threadIdx.x >> 7) * 64;

    #pragma unroll
    for (int mf = 0; mf < 2; mf++) {
        const int m  = m0 + wm + 16 * mf + g;
        const int b0r = m >> 11;          // batch
        const int i0r = m & (SEQ - 1);
        const int b1r = (m + 8) >> 11;
        const int i1r = (m + 8) & (SEQ - 1);
        #pragma unroll
        for (int nf = 0; nf < 8; nf++) {
            const int o = n0 + wn + 8 * nf + 2 * tg;
            const int h = o >> 6;
            const int d = o & (HD - 1);
            const float bx = __ldg(&bias[o]);
            const float by = __ldg(&bias[o + 1]);
            *(float2*)&dst[(((size_t)(b0r * NH + h) * SEQ + i0r) * HD) + d] =
                make_float2(c[mf][nf][0] + bx, c[mf][nf][1] + by);
            *(float2*)&dst[(((size_t)(b1r * NH + h) * SEQ + i1r) * HD) + d] =
                make_float2(c[mf][nf][2] + bx, c[mf][nf][3] + by);
        }
    }
}

// ---------------------------------------------------------------------------
// Fused flash attention + edge MLP, tf32 tensor cores. (proven in R3)
// ---------------------------------------------------------------------------
__global__ __launch_bounds__(128, 2) void attn_kernel(
    const float* __restrict__ adj,
    const float* __restrict__ We1, const float* __restrict__ be1,
    const float* __restrict__ We2, const float* __restrict__ be2,
    const float* __restrict__ ebias)
{
    const int LDP = 72;
    __shared__ float SA[64 * 72];
    __shared__ float SB[64 * 72];
    __shared__ float ew1[EDIM], eb1[EDIM], ew2[EDIM];

    const int h   = blockIdx.x;
    const int i0  = blockIdx.y * 64;
    const int b   = blockIdx.z;
    const int tid = threadIdx.x;
    const int w   = tid >> 5;
    const int ln  = tid & 31;
    const int g   = ln >> 2;
    const int tg  = ln & 3;
    const int rl  = 16 * w + g;

    const float* qbase = g_q + (size_t)(b * NH + h) * SEQ * HD;
    const float* kbase = g_k + (size_t)(b * NH + h) * SEQ * HD;
    const float* vbase = g_v + (size_t)(b * NH + h) * SEQ * HD;
    const float* abase = adj + (size_t)b * SEQ * SEQ;

    if (tid < EDIM) {
        ew1[tid] = We1[tid];
        eb1[tid] = be1[tid];
        ew2[tid] = We2[h * EDIM + tid];
    }
    const float c2 = __ldg(&be2[h]);
    const float eb = __ldg(&ebias[h]);

    #pragma unroll
    for (int p = 0; p < 8; p++) {
        const int idx = p * 128 + tid;
        const int row = idx >> 4;
        const int c4  = (idx & 15) << 2;
        float4 v = *(const float4*)&qbase[(size_t)(i0 + row) * HD + c4];
        *(uint4*)&SA[row * LDP + c4] = make_uint4(f2t(v.x), f2t(v.y), f2t(v.z), f2t(v.w));
    }
    __syncthreads();

    unsigned Qf[8][4];
    #pragma unroll
    for (int k0 = 0; k0 < 8; k0++) {
        Qf[k0][0] = __float_as_uint(SA[(rl    ) * LDP + 8 * k0 + tg    ]);
        Qf[k0][1] = __float_as_uint(SA[(rl + 8) * LDP + 8 * k0 + tg    ]);
        Qf[k0][2] = __float_as_uint(SA[(rl    ) * LDP + 8 * k0 + tg + 4]);
        Qf[k0][3] = __float_as_uint(SA[(rl + 8) * LDP + 8 * k0 + tg + 4]);
    }

    float O[8][4];
    #pragma unroll
    for (int nt = 0; nt < 8; nt++)
        #pragma unroll
        for (int c = 0; c < 4; c++) O[nt][c] = 0.f;
    float m0 = -3.0e38f, m1 = -3.0e38f, l0 = 0.f, l1 = 0.f;
    const float scale = 0.125f;

    for (int jt = 0; jt < SEQ / 64; jt++) {
        const int j0 = jt * 64;
        __syncthreads();

        #pragma unroll
        for (int p = 0; p < 8; p++) {
            const int idx = p * 128 + tid;
            const int row = idx >> 4;
            const int c4  = (idx & 15) << 2;
            float4 kv = *(const float4*)&kbase[(size_t)(j0 + row) * HD + c4];
            *(uint4*)&SA[row * LDP + c4] = make_uint4(f2t(kv.x), f2t(kv.y), f2t(kv.z), f2t(kv.w));
            float4 vv = *(const float4*)&vbase[(size_t)(j0 + row) * HD + c4];
            *(uint4*)&SB[row * LDP + c4] = make_uint4(f2t(vv.x), f2t(vv.y), f2t(vv.z), f2t(vv.w));
        }
        __syncthreads();

        float2 aL[8], aH[8];
        #pragma unroll
        for (int nt = 0; nt < 8; nt++) {
            const int col = j0 + 8 * nt + 2 * tg;
            aL[nt] = __ldg((const float2*)&abase[(size_t)(i0 + rl    ) * SEQ + col]);
            aH[nt] = __ldg((const float2*)&abase[(size_t)(i0 + rl + 8) * SEQ + col]);
        }

        float S[8][4];
        #pragma unroll
        for (int nt = 0; nt < 8; nt++)
            #pragma unroll
            for (int c = 0; c < 4; c++) S[nt][c] = 0.f;

        #pragma unroll
        for (int k0 = 0; k0 < 8; k0++) {
            #pragma unroll
            for (int nt = 0; nt < 8; nt++) {
                unsigned b0 = __float_as_uint(SA[(8 * nt + g) * LDP + 8 * k0 + tg    ]);
                unsigned b1 = __float_as_uint(SA[(8 * nt + g) * LDP + 8 * k0 + tg + 4]);
                mma8(S[nt][0], S[nt][1], S[nt][2], S[nt][3],
                     Qf[k0][0], Qf[k0][1], Qf[k0][2], Qf[k0][3], b0, b1);
            }
        }
        __syncthreads();

        #pragma unroll
        for (int nt = 0; nt < 8; nt++) {
            S[nt][0] = fmaf(S[nt][0], scale, fmaf(aL[nt].x, eb, c2));
            S[nt][1] = fmaf(S[nt][1], scale, fmaf(aL[nt].y, eb, c2));
            S[nt][2] = fmaf(S[nt][2], scale, fmaf(aH[nt].x, eb, c2));
            S[nt][3] = fmaf(S[nt][3], scale, fmaf(aH[nt].y, eb, c2));
        }
        #pragma unroll 1
        for (int e = 0; e < EDIM; e++) {
            const float w1e = ew1[e], b1e = eb1[e], w2e = ew2[e];
            #pragma unroll
            for (int nt = 0; nt < 8; nt++) {
                S[nt][0] = fmaf(fmaxf(fmaf(aL[nt].x, w1e, b1e), 0.f), w2e, S[nt][0]);
                S[nt][1] = fmaf(fmaxf(fmaf(aL[nt].y, w1e, b1e), 0.f), w2e, S[nt][1]);
                S[nt][2] = fmaf(fmaxf(fmaf(aH[nt].x, w1e, b1e), 0.f), w2e, S[nt][2]);
                S[nt][3] = fmaf(fmaxf(fmaf(aH[nt].y, w1e, b1e), 0.f), w2e, S[nt][3]);
            }
        }

        float mt0 = -3.0e38f, mt1 = -3.0e38f;
        #pragma unroll
        for (int nt = 0; nt < 8; nt++) {
            mt0 = fmaxf(mt0, fmaxf(S[nt][0], S[nt][1]));
            mt1 = fmaxf(mt1, fmaxf(S[nt][2], S[nt][3]));
        }
        mt0 = fmaxf(mt0, __shfl_xor_sync(0xffffffffu, mt0, 1));
        mt0 = fmaxf(mt0, __shfl_xor_sync(0xffffffffu, mt0, 2));
        mt1 = fmaxf(mt1, __shfl_xor_sync(0xffffffffu, mt1, 1));
        mt1 = fmaxf(mt1, __shfl_xor_sync(0xffffffffu, mt1, 2));

        const float mn0 = fmaxf(m0, mt0);
        const float mn1 = fmaxf(m1, mt1);
        const float cr0 = __expf(m0 - mn0);
        const float cr1 = __expf(m1 - mn1);
        m0 = mn0; m1 = mn1;

        float rs0 = 0.f, rs1 = 0.f;
        #pragma unroll
        for (int nt = 0; nt < 8; nt++) {
            S[nt][0] = __expf(S[nt][0] - mn0);
            S[nt][1] = __expf(S[nt][1] - mn0);
            S[nt][2] = __expf(S[nt][2] - mn1);
            S[nt][3] = __expf(S[nt][3] - mn1);
            rs0 += S[nt][0] + S[nt][1];
            rs1 += S[nt][2] + S[nt][3];
        }
        rs0 += __shfl_xor_sync(0xffffffffu, rs0, 1);
        rs0 += __shfl_xor_sync(0xffffffffu, rs0, 2);
        rs1 += __shfl_xor_sync(0xffffffffu, rs1, 1);
        rs1 += __shfl_xor_sync(0xffffffffu, rs1, 2);
        l0 = l0 * cr0 + rs0;
        l1 = l1 * cr1 + rs1;

        #pragma unroll
        for (int nt = 0; nt < 8; nt++) {
            O[nt][0] *= cr0; O[nt][1] *= cr0;
            O[nt][2] *= cr1; O[nt][3] *= cr1;
        }

        #pragma unroll
        for (int nt = 0; nt < 8; nt++) {
            *(float2*)&SA[(rl    ) * LDP + 8 * nt + 2 * tg] =
                make_float2(__uint_as_float(f2t(S[nt][0])), __uint_as_float(f2t(S[nt][1])));
            *(float2*)&SA[(rl + 8) * LDP + 8 * nt + 2 * tg] =
                make_float2(__uint_as_float(f2t(S[nt][2])), __uint_as_float(f2t(S[nt][3])));
        }
        __syncwarp();

        #pragma unroll
        for (int k0 = 0; k0 < 8; k0++) {
            unsigned pa0 = __float_as_uint(SA[(rl    ) * LDP + 8 * k0 + tg    ]);
            unsigned pa1 = __float_as_uint(SA[(rl + 8) * LDP + 8 * k0 + tg    ]);
            unsigned pa2 = __float_as_uint(SA[(rl    ) * LDP + 8 * k0 + tg + 4]);
            unsigned pa3 = __float_as_uint(SA[(rl + 8) * LDP + 8 * k0 + tg + 4]);
            #pragma unroll
            for (int nt = 0; nt < 8; nt++) {
                unsigned b0 = __float_as_uint(SB[(8 * k0 + tg    ) * LDP + 8 * nt + g]);
                unsigned b1 = __float_as_uint(SB[(8 * k0 + tg + 4) * LDP + 8 * nt + g]);
                mma8(O[nt][0], O[nt][1], O[nt][2], O[nt][3], pa0, pa1, pa2, pa3, b0, b1);
            }
        }
    }

    const float iv0 = 1.f / l0;
    const float iv1 = 1.f / l1;
    float* ob = g_ao + (size_t)(b * SEQ + i0 + rl) * EMB + h * HD;
    #pragma unroll
    for (int nt = 0; nt < 8; nt++) {
        *(float2*)&ob[8 * nt + 2 * tg] = make_float2(O[nt][0] * iv0, O[nt][1] * iv0);
        *(float2*)&ob[(size_t)8 * EMB + 8 * nt + 2 * tg] = make_float2(O[nt][2] * iv1, O[nt][3] * iv1);
    }
}

// ---------------------------------------------------------------------------
// Output projection (tf32 mma): out = g_ao @ Wo^T + bo (row-major)
// ---------------------------------------------------------------------------
__global__ __launch_bounds__(256, 2) void oproj_kernel(
    const float* __restrict__ Wo, const float* __restrict__ bo,
    float* __restrict__ out)
{
    const int m0 = blockIdx.y * 128;
    const int n0 = blockIdx.x * 128;

    float c[2][8][4];
    #pragma unroll
    for (int mf = 0; mf < 2; mf++)
        #pragma unroll
        for (int nf = 0; nf < 8; nf++)
            #pragma unroll
            for (int q = 0; q < 4; q++) c[mf][nf][q] = 0.f;

    gemm_tf32_core(g_ao, Wo, m0, n0, c);

    const int ln = threadIdx.x & 31;
    const int g  = ln >> 2;
    const int tg = ln & 3;
    const int wm = ((threadIdx.x >> 5) & 3) * 32;
    const int wn = (threadIdx.x >> 7) * 64;

    #pragma unroll
    for (int mf = 0; mf < 2; mf++) {
        const int m = m0 + wm + 16 * mf + g;
        #pragma unroll
        for (int nf = 0; nf < 8; nf++) {
            const int o = n0 + wn + 8 * nf + 2 * tg;
            const float bx = __ldg(&bo[o]);
            const float by = __ldg(&bo[o + 1]);
            *(float2*)&out[(size_t)m * EMB + o] =
                make_float2(c[mf][nf][0] + bx, c[mf][nf][1] + by);
            *(float2*)&out[(size_t)(m + 8) * EMB + o] =
                make_float2(c[mf][nf][2] + bx, c[mf][nf][3] + by);
        }
    }
}

// ---------------------------------------------------------------------------
extern "C" void kernel_launch(void* const* d_in, const int* in_sizes, int n_in,
                              void* d_out, int out_size)
{
    const float* x   = (const float*)d_in[0];
    const float* adj = (const float*)d_in[1];
    const float* Wq  = (const float*)d_in[2];
    const float* bq  = (const float*)d_in[3];
    const float* Wk  = (const float*)d_in[4];
    const float* bk  = (const float*)d_in[5];
    const float* Wv  = (const float*)d_in[6];
    const float* bv  = (const float*)d_in[7];
    const float* Wo  = (const float*)d_in[8];
    const float* bo  = (const float*)d_in[9];
    const float* We1 = (const float*)d_in[10];
    const float* be1 = (const float*)d_in[11];
    const float* We2 = (const float*)d_in[12];
    const float* be2 = (const float*)d_in[13];
    const float* eb  = (const float*)d_in[14];
    float* out = (float*)d_out;

    qkv_kernel<<<dim3(EMB / 128, MROWS / 128, 3), 256>>>(x, Wq, bq, Wk, bk, Wv, bv);
    attn_kernel<<<dim3(NH, SEQ / 64, BATCH), 128>>>(adj, We1, be1, We2, be2, eb);
    oproj_kernel<<<dim3(EMB / 128, MROWS / 128), 256>>>(Wo, bo, out);
}